// round 2
// baseline (speedup 1.0000x reference)
#include <cuda_runtime.h>
#include <math_constants.h>
#include <float.h>

#define BB 4
#define LL 512
#define EE 1024
#define HH 128

// Scratch (allocation-free rule: device globals)
__device__ float g_rec_hid[BB*LL*HH];
__device__ float g_lig_hid[BB*LL*HH];
__device__ unsigned int g_max[BB];

// ---------------------------------------------------------------------------
// Kernel 1: hid = relu(emb @ W1 + b1)  for both rec and lig (blockIdx.y picks)
// M = B*L = 2048, K = E = 1024, N = H = 128
// Tile: BM=32 x BN=128, BK=32, 256 threads, thread tile 2x8
// ---------------------------------------------------------------------------
#define BM 32
#define BN 128
#define BK 32

__global__ void gemm_relu_kernel(const float* __restrict__ rec,
                                 const float* __restrict__ lig,
                                 const float* __restrict__ W,
                                 const float* __restrict__ bias) {
    __shared__ float As[BK*(BM+1)];   // [k][m], stride 33
    __shared__ float Bs[BK*BN];       // [k][n]

    const float* A = blockIdx.y ? lig : rec;
    float*       C = blockIdx.y ? g_lig_hid : g_rec_hid;

    const int t  = threadIdx.x;
    const int m0 = blockIdx.x * BM;
    const int tx = t & 15;   // n-group: cols [tx*8, tx*8+8)
    const int ty = t >> 4;   // m-group: rows {ty*2, ty*2+1}

    float acc[2][8];
    #pragma unroll
    for (int i = 0; i < 2; i++)
        #pragma unroll
        for (int j = 0; j < 8; j++) acc[i][j] = 0.f;

    const int ak = t & 31;        // k index for A loads
    const int am = t >> 5;        // m base (0..7), step 8
    const int bn = (t & 31) * 4;  // n index for B float4 loads
    const int bk = t >> 5;        // k base (0..7), step 8

    for (int kk = 0; kk < EE; kk += BK) {
        #pragma unroll
        for (int r = 0; r < 4; r++) {
            int m = am + r * 8;
            As[ak*(BM+1) + m] = A[(m0 + m)*EE + kk + ak];
        }
        #pragma unroll
        for (int r = 0; r < 4; r++) {
            int k = bk + r * 8;
            *(float4*)&Bs[k*BN + bn] = *(const float4*)&W[(kk + k)*HH + bn];
        }
        __syncthreads();

        #pragma unroll
        for (int k = 0; k < BK; k++) {
            float a0 = As[k*(BM+1) + ty*2];
            float a1 = As[k*(BM+1) + ty*2 + 1];
            float4 p0 = *(float4*)&Bs[k*BN + tx*8];
            float4 p1 = *(float4*)&Bs[k*BN + tx*8 + 4];
            acc[0][0] = fmaf(a0, p0.x, acc[0][0]);
            acc[0][1] = fmaf(a0, p0.y, acc[0][1]);
            acc[0][2] = fmaf(a0, p0.z, acc[0][2]);
            acc[0][3] = fmaf(a0, p0.w, acc[0][3]);
            acc[0][4] = fmaf(a0, p1.x, acc[0][4]);
            acc[0][5] = fmaf(a0, p1.y, acc[0][5]);
            acc[0][6] = fmaf(a0, p1.z, acc[0][6]);
            acc[0][7] = fmaf(a0, p1.w, acc[0][7]);
            acc[1][0] = fmaf(a1, p0.x, acc[1][0]);
            acc[1][1] = fmaf(a1, p0.y, acc[1][1]);
            acc[1][2] = fmaf(a1, p0.z, acc[1][2]);
            acc[1][3] = fmaf(a1, p0.w, acc[1][3]);
            acc[1][4] = fmaf(a1, p1.x, acc[1][4]);
            acc[1][5] = fmaf(a1, p1.y, acc[1][5]);
            acc[1][6] = fmaf(a1, p1.z, acc[1][6]);
            acc[1][7] = fmaf(a1, p1.w, acc[1][7]);
        }
        __syncthreads();
    }

    #pragma unroll
    for (int rm = 0; rm < 2; rm++) {
        int row = m0 + ty*2 + rm;
        #pragma unroll
        for (int c = 0; c < 8; c++) {
            float v = acc[rm][c] + bias[tx*8 + c];
            C[row*HH + tx*8 + c] = fmaxf(v, 0.f);
        }
    }
}

// ---------------------------------------------------------------------------
// Kernel 2: fused tanh-outer-product + conv + pool + global max per batch.
// Block = 32x32 y-tile. Computes S grid 33x33 (halo via exact zero rows that
// reproduce conv zero-padding), then y and block max -> atomicMax (ordered u32).
// ---------------------------------------------------------------------------
#define TS 32
#define SD 33

__global__ void pair_kernel(const float* __restrict__ conv_w) {
    extern __shared__ float sm[];
    float*  r_s = sm;                 // [H][SD], h-major
    float*  l_s = sm + HH*SD;         // [H][SD]
    float4* S_s = (float4*)(sm + 2*HH*SD);   // [SD*SD]  (S00,S01,S10,S11)
    float4* w_s = S_s + SD*SD;               // [H]

    const int b   = blockIdx.z;
    const int i0  = blockIdx.y * TS;
    const int j0  = blockIdx.x * TS;
    const int tid = threadIdx.x;

    if (tid < HH) w_s[tid] = ((const float4*)conv_w)[tid];

    const float* rbase = g_rec_hid + b*LL*HH;
    const float* lbase = g_lig_hid + b*LL*HH;
    for (int idx = tid; idx < SD*HH; idx += blockDim.x) {
        int si = idx >> 7;          // / 128
        int h  = idx & (HH - 1);
        int gi = i0 - 1 + si;
        int gj = j0 - 1 + si;
        r_s[h*SD + si] = (gi >= 0) ? rbase[gi*HH + h] : 0.f;
        l_s[h*SD + si] = (gj >= 0) ? lbase[gj*HH + h] : 0.f;
    }
    __syncthreads();

    for (int pos = tid; pos < SD*SD; pos += blockDim.x) {
        int ii = pos / SD;
        int jj = pos - ii*SD;
        const float* rp = r_s + ii;
        const float* lp = l_s + jj;
        float s00 = 0.f, s01 = 0.f, s10 = 0.f, s11 = 0.f;
        #pragma unroll 8
        for (int h = 0; h < HH; h++) {
            float x = rp[h*SD] * lp[h*SD];
            float tnh;
            asm("tanh.approx.f32 %0, %1;" : "=f"(tnh) : "f"(x));
            float4 w = w_s[h];
            s00 = fmaf(tnh, w.x, s00);
            s01 = fmaf(tnh, w.y, s01);
            s10 = fmaf(tnh, w.z, s10);
            s11 = fmaf(tnh, w.w, s11);
        }
        S_s[pos] = make_float4(s00, s01, s10, s11);
    }
    __syncthreads();

    // y[i0+yi, j0+yj] = S00(yi,yj) + S01(yi,yj+1) + S10(yi+1,yj) + S11(yi+1,yj+1)
    float m = -CUDART_INF_F;
    for (int p = tid; p < TS*TS; p += blockDim.x) {
        int yi = p >> 5;
        int yj = p & 31;
        float4 a = S_s[yi*SD + yj];
        float4 q = S_s[yi*SD + yj + 1];
        float4 c = S_s[(yi+1)*SD + yj];
        float4 d = S_s[(yi+1)*SD + yj + 1];
        float y = (a.x + q.y) + (c.z + d.w);
        m = fmaxf(m, y);
    }
    #pragma unroll
    for (int o = 16; o; o >>= 1)
        m = fmaxf(m, __shfl_xor_sync(0xffffffffu, m, o));

    __shared__ float wmax[8];
    if ((tid & 31) == 0) wmax[tid >> 5] = m;
    __syncthreads();
    if (tid < 8) {
        m = wmax[tid];
        #pragma unroll
        for (int o = 4; o; o >>= 1)
            m = fmaxf(m, __shfl_xor_sync(0xffu, m, o));
        if (tid == 0) {
            unsigned u = __float_as_uint(m);
            u = (u & 0x80000000u) ? ~u : (u | 0x80000000u);
            atomicMax(&g_max[b], u);
        }
    }
}

// ---------------------------------------------------------------------------
__global__ void init_kernel() {
    if (threadIdx.x < BB) g_max[threadIdx.x] = 0u;
}

__global__ void final_kernel(const float* __restrict__ conv_b,
                             float* __restrict__ out) {
    int b = threadIdx.x;
    if (b < BB) {
        unsigned u = g_max[b];
        u = (u & 0x80000000u) ? (u ^ 0x80000000u) : ~u;
        float m = __uint_as_float(u) + conv_b[0];
        out[b] = 1.f / (1.f + expf(-m));
    }
}

// ---------------------------------------------------------------------------
extern "C" void kernel_launch(void* const* d_in, const int* in_sizes, int n_in,
                              void* d_out, int out_size) {
    const float* rec = (const float*)d_in[0];
    const float* lig = (const float*)d_in[1];
    const float* W1  = (const float*)d_in[2];
    const float* b1  = (const float*)d_in[3];
    const float* cw  = (const float*)d_in[4];
    const float* cb  = (const float*)d_in[5];

    const int pair_smem = (2*HH*SD)*(int)sizeof(float)
                        + (SD*SD + HH)*(int)sizeof(float4);   // 53264 B
    cudaFuncSetAttribute(pair_kernel,
                         cudaFuncAttributeMaxDynamicSharedMemorySize, pair_smem);

    init_kernel<<<1, 32>>>();
    gemm_relu_kernel<<<dim3((BB*LL)/BM, 2), 256>>>(rec, lig, W1, b1);
    pair_kernel<<<dim3(LL/TS, LL/TS, BB), 256, pair_smem>>>(cw);
    final_kernel<<<1, 32>>>(cb, (float*)d_out);
}

// round 3
// speedup vs baseline: 1.0573x; 1.0573x over previous
#include <cuda_runtime.h>
#include <math_constants.h>
#include <float.h>

#define BB 4
#define LL 512
#define EE 1024
#define HH 128

// Scratch (allocation-free rule: device globals)
__device__ float g_rec_hid[BB*LL*HH];
__device__ float g_lig_hid[BB*LL*HH];
__device__ unsigned int g_max[BB];

// ---------------------------------------------------------------------------
// Kernel 1: hid = relu(emb @ W1 + b1)  for both rec and lig (blockIdx.y picks)
// M = B*L = 2048, K = E = 1024, N = H = 128
// Tile: BM=32 x BN=128, BK=32, 256 threads, thread tile 2x8
// ---------------------------------------------------------------------------
#define BM 32
#define BN 128
#define BK 32

__global__ void gemm_relu_kernel(const float* __restrict__ rec,
                                 const float* __restrict__ lig,
                                 const float* __restrict__ W,
                                 const float* __restrict__ bias) {
    __shared__ float As[BK*(BM+1)];   // [k][m], stride 33
    __shared__ float Bs[BK*BN];       // [k][n]

    const float* A = blockIdx.y ? lig : rec;
    float*       C = blockIdx.y ? g_lig_hid : g_rec_hid;

    const int t  = threadIdx.x;
    const int m0 = blockIdx.x * BM;
    const int tx = t & 15;   // n-group: cols [tx*8, tx*8+8)
    const int ty = t >> 4;   // m-group: rows {ty*2, ty*2+1}

    float acc[2][8];
    #pragma unroll
    for (int i = 0; i < 2; i++)
        #pragma unroll
        for (int j = 0; j < 8; j++) acc[i][j] = 0.f;

    const int ak = t & 31;        // k index for A loads
    const int am = t >> 5;        // m base (0..7), step 8
    const int bn = (t & 31) * 4;  // n index for B float4 loads
    const int bk = t >> 5;        // k base (0..7), step 8

    for (int kk = 0; kk < EE; kk += BK) {
        #pragma unroll
        for (int r = 0; r < 4; r++) {
            int m = am + r * 8;
            As[ak*(BM+1) + m] = A[(m0 + m)*EE + kk + ak];
        }
        #pragma unroll
        for (int r = 0; r < 4; r++) {
            int k = bk + r * 8;
            *(float4*)&Bs[k*BN + bn] = *(const float4*)&W[(kk + k)*HH + bn];
        }
        __syncthreads();

        #pragma unroll
        for (int k = 0; k < BK; k++) {
            float a0 = As[k*(BM+1) + ty*2];
            float a1 = As[k*(BM+1) + ty*2 + 1];
            float4 p0 = *(float4*)&Bs[k*BN + tx*8];
            float4 p1 = *(float4*)&Bs[k*BN + tx*8 + 4];
            acc[0][0] = fmaf(a0, p0.x, acc[0][0]);
            acc[0][1] = fmaf(a0, p0.y, acc[0][1]);
            acc[0][2] = fmaf(a0, p0.z, acc[0][2]);
            acc[0][3] = fmaf(a0, p0.w, acc[0][3]);
            acc[0][4] = fmaf(a0, p1.x, acc[0][4]);
            acc[0][5] = fmaf(a0, p1.y, acc[0][5]);
            acc[0][6] = fmaf(a0, p1.z, acc[0][6]);
            acc[0][7] = fmaf(a0, p1.w, acc[0][7]);
            acc[1][0] = fmaf(a1, p0.x, acc[1][0]);
            acc[1][1] = fmaf(a1, p0.y, acc[1][1]);
            acc[1][2] = fmaf(a1, p0.z, acc[1][2]);
            acc[1][3] = fmaf(a1, p0.w, acc[1][3]);
            acc[1][4] = fmaf(a1, p1.x, acc[1][4]);
            acc[1][5] = fmaf(a1, p1.y, acc[1][5]);
            acc[1][6] = fmaf(a1, p1.z, acc[1][6]);
            acc[1][7] = fmaf(a1, p1.w, acc[1][7]);
        }
        __syncthreads();
    }

    #pragma unroll
    for (int rm = 0; rm < 2; rm++) {
        int row = m0 + ty*2 + rm;
        #pragma unroll
        for (int c = 0; c < 8; c++) {
            float v = acc[rm][c] + bias[tx*8 + c];
            C[row*HH + tx*8 + c] = fmaxf(v, 0.f);
        }
    }
}

// ---------------------------------------------------------------------------
// Kernel 2: fused tanh-outer-product + conv + pool + global max per batch.
// Block = 32x32 y-tile. Computes S grid 33x33 (halo via exact zero rows that
// reproduce conv zero-padding), then y and block max -> atomicMax (ordered u32).
// ---------------------------------------------------------------------------
#define TS 32
#define SD 33

__global__ void pair_kernel(const float* __restrict__ conv_w) {
    extern __shared__ float sm[];
    float*  r_s = sm;                 // [H][SD], h-major
    float*  l_s = sm + HH*SD;         // [H][SD]
    float4* S_s = (float4*)(sm + 2*HH*SD);   // [SD*SD]  (S00,S01,S10,S11)
    float4* w_s = S_s + SD*SD;               // [H]

    const int b   = blockIdx.z;
    const int i0  = blockIdx.y * TS;
    const int j0  = blockIdx.x * TS;
    const int tid = threadIdx.x;

    if (tid < HH) w_s[tid] = ((const float4*)conv_w)[tid];

    const float* rbase = g_rec_hid + b*LL*HH;
    const float* lbase = g_lig_hid + b*LL*HH;
    for (int idx = tid; idx < SD*HH; idx += blockDim.x) {
        int si = idx >> 7;          // / 128
        int h  = idx & (HH - 1);
        int gi = i0 - 1 + si;
        int gj = j0 - 1 + si;
        r_s[h*SD + si] = (gi >= 0) ? rbase[gi*HH + h] : 0.f;
        l_s[h*SD + si] = (gj >= 0) ? lbase[gj*HH + h] : 0.f;
    }
    __syncthreads();

    for (int pos = tid; pos < SD*SD; pos += blockDim.x) {
        int ii = pos / SD;
        int jj = pos - ii*SD;
        const float* rp = r_s + ii;
        const float* lp = l_s + jj;
        float s00 = 0.f, s01 = 0.f, s10 = 0.f, s11 = 0.f;
        #pragma unroll 8
        for (int h = 0; h < HH; h++) {
            float x = rp[h*SD] * lp[h*SD];
            float tnh;
            asm("tanh.approx.f32 %0, %1;" : "=f"(tnh) : "f"(x));
            float4 w = w_s[h];
            s00 = fmaf(tnh, w.x, s00);
            s01 = fmaf(tnh, w.y, s01);
            s10 = fmaf(tnh, w.z, s10);
            s11 = fmaf(tnh, w.w, s11);
        }
        S_s[pos] = make_float4(s00, s01, s10, s11);
    }
    __syncthreads();

    // y[i0+yi, j0+yj] = S00(yi,yj) + S01(yi,yj+1) + S10(yi+1,yj) + S11(yi+1,yj+1)
    float m = -CUDART_INF_F;
    for (int p = tid; p < TS*TS; p += blockDim.x) {
        int yi = p >> 5;
        int yj = p & 31;
        float4 a = S_s[yi*SD + yj];
        float4 q = S_s[yi*SD + yj + 1];
        float4 c = S_s[(yi+1)*SD + yj];
        float4 d = S_s[(yi+1)*SD + yj + 1];
        float y = (a.x + q.y) + (c.z + d.w);
        m = fmaxf(m, y);
    }
    #pragma unroll
    for (int o = 16; o; o >>= 1)
        m = fmaxf(m, __shfl_xor_sync(0xffffffffu, m, o));

    __shared__ float wmax[8];
    if ((tid & 31) == 0) wmax[tid >> 5] = m;
    __syncthreads();
    if (tid < 8) {
        m = wmax[tid];
        #pragma unroll
        for (int o = 4; o; o >>= 1)
            m = fmaxf(m, __shfl_xor_sync(0xffu, m, o));
        if (tid == 0) {
            unsigned u = __float_as_uint(m);
            u = (u & 0x80000000u) ? ~u : (u | 0x80000000u);
            atomicMax(&g_max[b], u);
        }
    }
}

// ---------------------------------------------------------------------------
__global__ void init_kernel() {
    if (threadIdx.x < BB) g_max[threadIdx.x] = 0u;
}

__global__ void final_kernel(const float* __restrict__ conv_b,
                             float* __restrict__ out) {
    int b = threadIdx.x;
    if (b < BB) {
        unsigned u = g_max[b];
        u = (u & 0x80000000u) ? (u ^ 0x80000000u) : ~u;
        float m = __uint_as_float(u) + conv_b[0];
        out[b] = 1.f / (1.f + expf(-m));
    }
}

// ---------------------------------------------------------------------------
extern "C" void kernel_launch(void* const* d_in, const int* in_sizes, int n_in,
                              void* d_out, int out_size) {
    const float* rec = (const float*)d_in[0];
    const float* lig = (const float*)d_in[1];
    const float* W1  = (const float*)d_in[2];
    const float* b1  = (const float*)d_in[3];
    const float* cw  = (const float*)d_in[4];
    const float* cb  = (const float*)d_in[5];

    const int pair_smem = (2*HH*SD)*(int)sizeof(float)
                        + (SD*SD + HH)*(int)sizeof(float4);   // 53264 B
    cudaFuncSetAttribute(pair_kernel,
                         cudaFuncAttributeMaxDynamicSharedMemorySize, pair_smem);

    init_kernel<<<1, 32>>>();
    gemm_relu_kernel<<<dim3((BB*LL)/BM, 2), 256>>>(rec, lig, W1, b1);
    pair_kernel<<<dim3(LL/TS, LL/TS, BB), 256, pair_smem>>>(cw);
    final_kernel<<<1, 32>>>(cb, (float*)d_out);
}